// round 5
// baseline (speedup 1.0000x reference)
#include <cuda_runtime.h>

#define HW      200704          // 448*448
#define WID     448
#define CC      64
#define BATCH   2
#define TG2     3136            // 56*56
#define P2      196
#define NPB     12845056        // C*HW per batch
#define SPB     65536           // S per batch
#define EPSV    1e-5f
#define GRIDK   74
#define KCHUNK  886             // ceil(65536/74)

// ---------------- scratch (device globals; no runtime allocation) ----------------
__device__ float g_q[BATCH * NPB];
__device__ float g_k[BATCH * NPB];
__device__ float g_v[BATCH * NPB];
__device__ float g_hin[BATCH * NPB];
__device__ float g_spart[BATCH * 784 * 2];
__device__ float g_stats[BATCH * 2];
__device__ float g_px[BATCH * CC * TG2];
__device__ float g_qg[BATCH * TG2 * CC];
__device__ float g_kg[BATCH * TG2 * CC];
__device__ float g_vg[BATCH * TG2 * CC];
__device__ float g_wmp[BATCH * GRIDK * P2 * P2];
__device__ float g_wm[BATCH * P2 * P2];
__device__ float g_wg[(size_t)BATCH * TG2 * TG2];
__device__ float g_hg[BATCH * TG2 * CC];

// ---------------- K1: 8x8 avg-pool of x + GN statistic partials ----------------
__global__ __launch_bounds__(256) void k_pool_stats(const float* __restrict__ x) {
    int b = blockIdx.y;
    int idx = blockIdx.x * 256 + threadIdx.x;      // 0..200703 (=64*3136)
    int c = idx / TG2;
    int cell = idx - c * TG2;
    int th = cell / 56, tw = cell - th * 56;
    const float* xp = x + ((size_t)b * CC + c) * HW + (size_t)(th * 8) * WID + tw * 8;
    float s = 0.f, s2 = 0.f;
#pragma unroll
    for (int r = 0; r < 8; r++)
#pragma unroll
        for (int j = 0; j < 8; j++) {
            float v = xp[r * WID + j];
            s += v; s2 += v * v;
        }
    g_px[(b * CC + c) * TG2 + cell] = s * (1.f / 64.f);

    __shared__ float r0[256], r1[256];
    int t = threadIdx.x;
    r0[t] = s; r1[t] = s2;
    __syncthreads();
    for (int o = 128; o > 0; o >>= 1) {
        if (t < o) { r0[t] += r0[t + o]; r1[t] += r1[t + o]; }
        __syncthreads();
    }
    if (t == 0) {
        g_spart[(b * 784 + blockIdx.x) * 2 + 0] = r0[0];
        g_spart[(b * 784 + blockIdx.x) * 2 + 1] = r1[0];
    }
}

// ---------------- K2: reduce stats partials (deterministic) ----------------
__global__ void k_stats2() {
    int b = blockIdx.x, t = threadIdx.x;
    float s = 0.f, s2 = 0.f;
    for (int i = t; i < 784; i += 256) {
        s  += g_spart[(b * 784 + i) * 2 + 0];
        s2 += g_spart[(b * 784 + i) * 2 + 1];
    }
    __shared__ float r0[256], r1[256];
    r0[t] = s; r1[t] = s2;
    __syncthreads();
    for (int o = 128; o > 0; o >>= 1) {
        if (t < o) { r0[t] += r0[t + o]; r1[t] += r1[t + o]; }
        __syncthreads();
    }
    if (t == 0) { g_stats[b * 2] = r0[0]; g_stats[b * 2 + 1] = r1[0]; }
}

// ---------------- K3: pooled qkv from pooled x (pool commutes with GN+conv) ----------------
__global__ void k_qkvg(const float* __restrict__ gnw, const float* __restrict__ gnb,
                       const float* __restrict__ qw, const float* __restrict__ qb,
                       const float* __restrict__ kw, const float* __restrict__ kb,
                       const float* __restrict__ vw, const float* __restrict__ vb) {
    int b = blockIdx.y, cell = blockIdx.x, o = threadIdx.x;
    float mean = g_stats[b * 2] * (1.f / (float)NPB);
    float var  = g_stats[b * 2 + 1] * (1.f / (float)NPB) - mean * mean;
    float inv  = rsqrtf(var + EPSV);
    __shared__ float xn[64];
    xn[o] = (g_px[(b * CC + o) * TG2 + cell] - mean) * inv * gnw[o] + gnb[o];
    __syncthreads();
    float aq = qb[o], ak = kb[o], av = vb[o];
#pragma unroll 8
    for (int j = 0; j < 64; j++) {
        float xv = xn[j];
        aq += qw[o * 64 + j] * xv;
        ak += kw[o * 64 + j] * xv;
        av += vw[o * 64 + j] * xv;
    }
    int off = (b * TG2 + cell) * CC + o;
    g_qg[off] = aq; g_kg[off] = ak; g_vg[off] = av;
}

// ---------------- K4: full-resolution GN + q/k/v 1x1 convs ----------------
__global__ __launch_bounds__(256) void k_qkv(const float* __restrict__ x,
                                             const float* __restrict__ gnw, const float* __restrict__ gnb,
                                             const float* __restrict__ W0, const float* __restrict__ B0,
                                             const float* __restrict__ W1, const float* __restrict__ B1,
                                             const float* __restrict__ W2, const float* __restrict__ B2) {
    __shared__ float sXn[64 * 64];       // [c][p]
    __shared__ float sW[64 * 65];
    __shared__ float sB[64];
    int b = blockIdx.y;
    int pix0 = blockIdx.x * 64;
    int t = threadIdx.x;
    float mean = g_stats[b * 2] * (1.f / (float)NPB);
    float inv  = rsqrtf(g_stats[b * 2 + 1] * (1.f / (float)NPB) - mean * mean + EPSV);

    for (int i = t; i < 4096; i += 256) {
        int c = i >> 6, p = i & 63;
        float v = x[((size_t)b * CC + c) * HW + pix0 + p];
        sXn[i] = (v - mean) * inv * gnw[c] + gnb[c];
    }
    const float* Ws[3] = {W0, W1, W2};
    const float* Bs[3] = {B0, B1, B2};
    float* Os[3] = {g_q, g_k, g_v};
    int og = t >> 4, pg = t & 15;

    for (int m = 0; m < 3; m++) {
        __syncthreads();                  // xn ready / previous sW reads done
        for (int i = t; i < 4096; i += 256) {
            int o = i >> 6, c = i & 63;
            sW[o * 65 + c] = Ws[m][i];
        }
        if (t < 64) sB[t] = Bs[m][t];
        __syncthreads();
        float acc[4][4];
#pragma unroll
        for (int j = 0; j < 4; j++) {
            float bb = sB[og * 4 + j];
            acc[j][0] = bb; acc[j][1] = bb; acc[j][2] = bb; acc[j][3] = bb;
        }
#pragma unroll 4
        for (int c = 0; c < 64; c++) {
            float4 xv = ((const float4*)sXn)[c * 16 + pg];
#pragma unroll
            for (int j = 0; j < 4; j++) {
                float w = sW[(og * 4 + j) * 65 + c];
                acc[j][0] += w * xv.x; acc[j][1] += w * xv.y;
                acc[j][2] += w * xv.z; acc[j][3] += w * xv.w;
            }
        }
        float* O = Os[m];
#pragma unroll
        for (int j = 0; j < 4; j++) {
            int o = og * 4 + j;
            float4 r = make_float4(acc[j][0], acc[j][1], acc[j][2], acc[j][3]);
            *(float4*)(O + ((size_t)b * CC + o) * HW + pix0 + pg * 4) = r;
        }
    }
}

// ---------------- K5: wm split-K GEMM  wm[p][q] = sum_s q[s][p]*k[s][q] ----------------
__global__ __launch_bounds__(784, 1) void k_wm() {
    int b = blockIdx.y, kb = blockIdx.x;
    int s0 = kb * KCHUNK;
    int send = min(s0 + KCHUNK, SPB);
    const float* Q = g_q + (size_t)b * NPB;
    const float* K = g_k + (size_t)b * NPB;
    __shared__ float qs[8 * 196];
    __shared__ float ks[8 * 196];
    int t = threadIdx.x;
    int ty = t / 28, tx = t - ty * 28;
    float acc[7][7];
#pragma unroll
    for (int i = 0; i < 7; i++)
#pragma unroll
        for (int j = 0; j < 7; j++) acc[i][j] = 0.f;

    for (int st = s0; st < send; st += 8) {
        __syncthreads();
        for (int i = t; i < 8 * 196; i += 784) {
            int r = i / 196, col = i - r * 196;
            int s = st + r;
            bool ok = (s < send);
            size_t off = (size_t)s * 196 + col;
            qs[i] = ok ? Q[off] : 0.f;
            ks[i] = ok ? K[off] : 0.f;
        }
        __syncthreads();
#pragma unroll
        for (int ss = 0; ss < 8; ss++) {
            float q7[7], k7[7];
#pragma unroll
            for (int i = 0; i < 7; i++) {
                q7[i] = qs[ss * 196 + ty * 7 + i];
                k7[i] = ks[ss * 196 + tx * 7 + i];
            }
#pragma unroll
            for (int i = 0; i < 7; i++)
#pragma unroll
                for (int j = 0; j < 7; j++) acc[i][j] += q7[i] * k7[j];
        }
    }
    float* out = g_wmp + ((size_t)b * GRIDK + kb) * (P2 * P2);
#pragma unroll
    for (int i = 0; i < 7; i++)
#pragma unroll
        for (int j = 0; j < 7; j++)
            out[(ty * 7 + i) * P2 + tx * 7 + j] = acc[i][j];
}

// ---------------- K6: reduce wm partials ----------------
__global__ void k_wm_reduce() {
    int idx = blockIdx.x * 256 + threadIdx.x;
    if (idx >= BATCH * P2 * P2) return;
    int b = idx / (P2 * P2);
    int pq = idx - b * (P2 * P2);
    float s = 0.f;
    for (int r = 0; r < GRIDK; r++)
        s += g_wmp[((size_t)b * GRIDK + r) * (P2 * P2) + pq];
    g_wm[idx] = s;
}

// ---------------- K7: softmax over wm rows (scale 1/256) ----------------
__global__ void k_softmax_wm() {
    int b = blockIdx.y, p = blockIdx.x, t = threadIdx.x;
    float* row = g_wm + ((size_t)b * P2 + p) * P2;
    __shared__ float red[256];
    float v = (t < P2) ? row[t] * (1.f / 256.f) : -3.0e38f;
    red[t] = v;
    __syncthreads();
    for (int o = 128; o > 0; o >>= 1) {
        if (t < o) red[t] = fmaxf(red[t], red[t + o]);
        __syncthreads();
    }
    float mx = red[0];
    __syncthreads();
    float e = (t < P2) ? __expf(v - mx) : 0.f;
    red[t] = e;
    __syncthreads();
    for (int o = 128; o > 0; o >>= 1) {
        if (t < o) red[t] += red[t + o];
        __syncthreads();
    }
    float inv = 1.f / red[0];
    if (t < P2) row[t] = e * inv;
}

// ---------------- K8: global logits wg[p][q] = qg[p].kg[q] / 8 ----------------
__global__ __launch_bounds__(256) void k_wg() {
    int b = blockIdx.z;
    int p0 = blockIdx.y * 64, q0 = blockIdx.x * 64;
    __shared__ float Qs[64 * 65], Ks[64 * 65];
    const float* Qg = g_qg + (size_t)b * TG2 * CC;
    const float* Kg = g_kg + (size_t)b * TG2 * CC;
    int t = threadIdx.x;
    for (int i = t; i < 4096; i += 256) {
        int r = i >> 6, c = i & 63;
        Qs[r * 65 + c] = Qg[(p0 + r) * 64 + c];
        Ks[r * 65 + c] = Kg[(q0 + r) * 64 + c];
    }
    __syncthreads();
    int ty = t >> 4, tx = t & 15;
    float acc[4][4];
#pragma unroll
    for (int i = 0; i < 4; i++)
#pragma unroll
        for (int j = 0; j < 4; j++) acc[i][j] = 0.f;
#pragma unroll 4
    for (int c = 0; c < 64; c++) {
        float a[4], bb[4];
#pragma unroll
        for (int i = 0; i < 4; i++) a[i] = Qs[(ty * 4 + i) * 65 + c];
#pragma unroll
        for (int j = 0; j < 4; j++) bb[j] = Ks[(tx * 4 + j) * 65 + c];
#pragma unroll
        for (int i = 0; i < 4; i++)
#pragma unroll
            for (int j = 0; j < 4; j++) acc[i][j] += a[i] * bb[j];
    }
    float* out = g_wg + (size_t)b * TG2 * TG2;
#pragma unroll
    for (int i = 0; i < 4; i++) {
        float4 r = make_float4(acc[i][0] * 0.125f, acc[i][1] * 0.125f,
                               acc[i][2] * 0.125f, acc[i][3] * 0.125f);
        *(float4*)(out + (size_t)(p0 + ty * 4 + i) * TG2 + q0 + tx * 4) = r;
    }
}

// ---------------- K9: softmax over wg rows (3136 wide) ----------------
__global__ void k_softmax_wg() {
    int b = blockIdx.y, p = blockIdx.x, t = threadIdx.x;
    float* row = g_wg + ((size_t)b * TG2 + p) * TG2;
    __shared__ float sv[TG2];
    __shared__ float red[256];
    float lm = -3.0e38f;
    for (int i = t; i < TG2; i += 256) {
        float v = row[i];
        sv[i] = v;
        lm = fmaxf(lm, v);
    }
    red[t] = lm;
    __syncthreads();
    for (int o = 128; o > 0; o >>= 1) {
        if (t < o) red[t] = fmaxf(red[t], red[t + o]);
        __syncthreads();
    }
    float mx = red[0];
    __syncthreads();
    float ls = 0.f;
    for (int i = t; i < TG2; i += 256) {
        float e = __expf(sv[i] - mx);
        sv[i] = e;
        ls += e;
    }
    red[t] = ls;
    __syncthreads();
    for (int o = 128; o > 0; o >>= 1) {
        if (t < o) red[t] += red[t + o];
        __syncthreads();
    }
    float inv = 1.f / red[0];
    for (int i = t; i < TG2; i += 256) row[i] = sv[i] * inv;
}

// ---------------- K10: hg[q][c] = sum_k wg[q][k] * vg[k][c] ----------------
__global__ __launch_bounds__(256) void k_hg() {
    int b = blockIdx.y;
    int q0 = blockIdx.x * 64;
    __shared__ float Ws[64][33];
    __shared__ float Vs[32][68];
    const float* Wg = g_wg + (size_t)b * TG2 * TG2;
    const float* Vg = g_vg + (size_t)b * TG2 * CC;
    int t = threadIdx.x;
    int ty = t >> 4, tx = t & 15;
    float acc[4][4];
#pragma unroll
    for (int i = 0; i < 4; i++)
#pragma unroll
        for (int j = 0; j < 4; j++) acc[i][j] = 0.f;

    for (int k0 = 0; k0 < TG2; k0 += 32) {
        __syncthreads();
        for (int i = t; i < 2048; i += 256) {
            int r = i >> 5, kk = i & 31;
            Ws[r][kk] = Wg[(size_t)(q0 + r) * TG2 + k0 + kk];
        }
        for (int i = t; i < 2048; i += 256) {
            int kk = i >> 6, c = i & 63;
            Vs[kk][c] = Vg[(k0 + kk) * 64 + c];
        }
        __syncthreads();
#pragma unroll 4
        for (int kk = 0; kk < 32; kk++) {
            float a[4], bb[4];
#pragma unroll
            for (int i = 0; i < 4; i++) a[i] = Ws[ty * 4 + i][kk];
#pragma unroll
            for (int j = 0; j < 4; j++) bb[j] = Vs[kk][tx * 4 + j];
#pragma unroll
            for (int i = 0; i < 4; i++)
#pragma unroll
                for (int j = 0; j < 4; j++) acc[i][j] += a[i] * bb[j];
        }
    }
#pragma unroll
    for (int i = 0; i < 4; i++)
#pragma unroll
        for (int j = 0; j < 4; j++)
            g_hg[(b * TG2 + q0 + ty * 4 + i) * 64 + tx * 4 + j] = acc[i][j];
}

// ---------------- K11: hp[s][q'] = sum_k wm[q'][k] * v[s][k]  (M=65536,N=196,K=196) ----
__global__ __launch_bounds__(448) void k_hp() {
    int b = blockIdx.y;
    int s0 = blockIdx.x * 64;
    __shared__ float As[64][29];          // v tile [row][k]
    __shared__ float Bs[28][197];         // wm^T tile [k][q']
    const float* V  = g_v  + (size_t)b * NPB;
    const float* WM = g_wm + (size_t)b * P2 * P2;
    int t = threadIdx.x;
    int rg = t / 28, cg = t - rg * 28;    // rg 0..15, cg 0..27
    float acc[4][7];
#pragma unroll
    for (int i = 0; i < 4; i++)
#pragma unroll
        for (int j = 0; j < 7; j++) acc[i][j] = 0.f;

    for (int k0 = 0; k0 < 196; k0 += 28) {
        __syncthreads();
        for (int i = t; i < 64 * 28; i += 448) {
            int r = i / 28, kk = i - r * 28;
            As[r][kk] = V[(size_t)(s0 + r) * 196 + k0 + kk];
        }
        for (int i = t; i < 28 * 196; i += 448) {
            int kk = i / 196, c = i - kk * 196;
            Bs[kk][c] = WM[c * 196 + k0 + kk];   // wm^T
        }
        __syncthreads();
#pragma unroll 7
        for (int kk = 0; kk < 28; kk++) {
            float a4[4], b7[7];
#pragma unroll
            for (int i = 0; i < 4; i++) a4[i] = As[rg * 4 + i][kk];
#pragma unroll
            for (int j = 0; j < 7; j++) b7[j] = Bs[kk][cg * 7 + j];
#pragma unroll
            for (int i = 0; i < 4; i++)
#pragma unroll
                for (int j = 0; j < 7; j++) acc[i][j] += a4[i] * b7[j];
        }
    }
    float* O = g_hin + (size_t)b * NPB;
#pragma unroll
    for (int i = 0; i < 4; i++)
#pragma unroll
        for (int j = 0; j < 7; j++)
            O[(size_t)(s0 + rg * 4 + i) * 196 + cg * 7 + j] = acc[i][j];
}

// ---------------- K12: proj conv fused with 0.75*hp + 0.25*upsample(hg) + residual ----
__global__ __launch_bounds__(256) void k_proj(const float* __restrict__ x,
                                              const float* __restrict__ pw,
                                              float* __restrict__ out) {
    __shared__ float sH[64 * 64];         // [c][p]
    __shared__ float sW[64 * 65];
    int b = blockIdx.y;
    int pix0 = blockIdx.x * 64;
    int t = threadIdx.x;
    int h = pix0 / WID, w0 = pix0 - h * WID;
    int cell0 = (h >> 3) * 56 + (w0 >> 3);

    for (int i = t; i < 4096; i += 256) {
        int c = i >> 6, p = i & 63;
        float hp = g_hin[(size_t)b * NPB + (size_t)c * HW + pix0 + p];
        float hg = g_hg[(b * TG2 + cell0 + (p >> 3)) * 64 + c];
        sH[i] = 0.75f * hp + 0.25f * hg;
    }
    for (int i = t; i < 4096; i += 256) {
        int o = i >> 6, c = i & 63;
        sW[o * 65 + c] = pw[i];
    }
    __syncthreads();

    int og = t >> 4, pg = t & 15;
    float acc[4][4];
#pragma unroll
    for (int i = 0; i < 4; i++)
#pragma unroll
        for (int j = 0; j < 4; j++) acc[i][j] = 0.f;
#pragma unroll 4
    for (int c = 0; c < 64; c++) {
        float4 xv = ((const float4*)sH)[c * 16 + pg];
#pragma unroll
        for (int j = 0; j < 4; j++) {
            float wv = sW[(og * 4 + j) * 65 + c];
            acc[j][0] += wv * xv.x; acc[j][1] += wv * xv.y;
            acc[j][2] += wv * xv.z; acc[j][3] += wv * xv.w;
        }
    }
#pragma unroll
    for (int j = 0; j < 4; j++) {
        int o = og * 4 + j;
        size_t base = ((size_t)b * CC + o) * HW + pix0 + pg * 4;
        float4 xr = *(const float4*)(x + base);
        float4 r = make_float4(acc[j][0] + xr.x, acc[j][1] + xr.y,
                               acc[j][2] + xr.z, acc[j][3] + xr.w);
        *(float4*)(out + base) = r;
    }
}

extern "C" void kernel_launch(void* const* d_in, const int* in_sizes, int n_in,
                              void* d_out, int out_size) {
    const float* x   = (const float*)d_in[0];
    const float* gnw = (const float*)d_in[1];
    const float* gnb = (const float*)d_in[2];
    const float* qw  = (const float*)d_in[3];
    const float* qb  = (const float*)d_in[4];
    const float* kw  = (const float*)d_in[5];
    const float* kb  = (const float*)d_in[6];
    const float* vw  = (const float*)d_in[7];
    const float* vb  = (const float*)d_in[8];
    const float* pw  = (const float*)d_in[9];
    float* out = (float*)d_out;

    k_pool_stats<<<dim3(784, BATCH), 256>>>(x);
    k_stats2<<<BATCH, 256>>>();
    k_qkvg<<<dim3(TG2, BATCH), 64>>>(gnw, gnb, qw, qb, kw, kb, vw, vb);
    k_qkv<<<dim3(HW / 64, BATCH), 256>>>(x, gnw, gnb, qw, qb, kw, kb, vw, vb);
    k_wm<<<dim3(GRIDK, BATCH), 784>>>();
    k_wm_reduce<<<(BATCH * P2 * P2 + 255) / 256, 256>>>();
    k_softmax_wm<<<dim3(P2, BATCH), 256>>>();
    k_wg<<<dim3(TG2 / 64, TG2 / 64, BATCH), 256>>>();
    k_softmax_wg<<<dim3(TG2, BATCH), 256>>>();
    k_hg<<<dim3(TG2 / 64, BATCH), 256>>>();
    k_hp<<<dim3(SPB / 64, BATCH), 448>>>();
    k_proj<<<dim3(HW / 64, BATCH), 256>>>(x, pw, out);
}

// round 6
// speedup vs baseline: 1.0189x; 1.0189x over previous
#include <cuda_runtime.h>

#define HW      200704          // 448*448
#define WID     448
#define CC      64
#define BATCH   2
#define TG2     3136            // 56*56
#define P2      196
#define NPB     12845056        // C*HW per batch
#define SPB     65536           // S per batch
#define EPSV    1e-5f
#define GRIDK   74
#define KCHUNK  886             // ceil(65536/74)

// ---------------- scratch ----------------
__device__ float g_q[BATCH * NPB];
__device__ float g_k[BATCH * NPB];
__device__ float g_v[BATCH * NPB];
__device__ float g_hin[BATCH * NPB];
__device__ float g_spart[BATCH * 784 * 2];
__device__ float g_stats[BATCH * 2];
__device__ float g_px[BATCH * CC * TG2];
__device__ float g_qg[BATCH * TG2 * CC];
__device__ float g_kg[BATCH * TG2 * CC];
__device__ float g_vg[BATCH * TG2 * CC];
__device__ float g_wmp[BATCH * GRIDK * P2 * P2];
__device__ float g_wmT[BATCH * P2 * P2];     // wmT[k][q] = softmax(wm)[q][k]
__device__ float g_wg[(size_t)BATCH * TG2 * TG2];
__device__ float g_hg[BATCH * TG2 * CC];

// ---------------- K1: 8x8 avg-pool of x + GN stat partials ----------------
__global__ __launch_bounds__(256) void k_pool_stats(const float* __restrict__ x) {
    int b = blockIdx.y;
    int idx = blockIdx.x * 256 + threadIdx.x;      // 0..200703
    int c = idx / TG2;
    int cell = idx - c * TG2;
    int th = cell / 56, tw = cell - th * 56;
    const float* xp = x + ((size_t)b * CC + c) * HW + (size_t)(th * 8) * WID + tw * 8;
    float s = 0.f, s2 = 0.f;
#pragma unroll
    for (int r = 0; r < 8; r++) {
        float4 a = *(const float4*)(xp + r * WID);
        float4 bb = *(const float4*)(xp + r * WID + 4);
        s  += a.x + a.y + a.z + a.w + bb.x + bb.y + bb.z + bb.w;
        s2 += a.x*a.x + a.y*a.y + a.z*a.z + a.w*a.w
            + bb.x*bb.x + bb.y*bb.y + bb.z*bb.z + bb.w*bb.w;
    }
    g_px[(b * CC + c) * TG2 + cell] = s * (1.f / 64.f);

    __shared__ float r0[256], r1[256];
    int t = threadIdx.x;
    r0[t] = s; r1[t] = s2;
    __syncthreads();
    for (int o = 128; o > 0; o >>= 1) {
        if (t < o) { r0[t] += r0[t + o]; r1[t] += r1[t + o]; }
        __syncthreads();
    }
    if (t == 0) {
        g_spart[(b * 784 + blockIdx.x) * 2 + 0] = r0[0];
        g_spart[(b * 784 + blockIdx.x) * 2 + 1] = r1[0];
    }
}

// ---------------- K2: reduce stat partials ----------------
__global__ void k_stats2() {
    int b = blockIdx.x, t = threadIdx.x;
    float s = 0.f, s2 = 0.f;
    for (int i = t; i < 784; i += 256) {
        s  += g_spart[(b * 784 + i) * 2 + 0];
        s2 += g_spart[(b * 784 + i) * 2 + 1];
    }
    __shared__ float r0[256], r1[256];
    r0[t] = s; r1[t] = s2;
    __syncthreads();
    for (int o = 128; o > 0; o >>= 1) {
        if (t < o) { r0[t] += r0[t + o]; r1[t] += r1[t + o]; }
        __syncthreads();
    }
    if (t == 0) { g_stats[b * 2] = r0[0]; g_stats[b * 2 + 1] = r1[0]; }
}

// ---------------- K3: pooled qkv from pooled x ----------------
__global__ void k_qkvg(const float* __restrict__ gnw, const float* __restrict__ gnb,
                       const float* __restrict__ qw, const float* __restrict__ qb,
                       const float* __restrict__ kw, const float* __restrict__ kb,
                       const float* __restrict__ vw, const float* __restrict__ vb) {
    int b = blockIdx.y, cell = blockIdx.x, o = threadIdx.x;
    float mean = g_stats[b * 2] * (1.f / (float)NPB);
    float var  = g_stats[b * 2 + 1] * (1.f / (float)NPB) - mean * mean;
    float inv  = rsqrtf(var + EPSV);
    __shared__ float xn[64];
    xn[o] = (g_px[(b * CC + o) * TG2 + cell] - mean) * inv * gnw[o] + gnb[o];
    __syncthreads();
    float aq = qb[o], ak = kb[o], av = vb[o];
#pragma unroll 8
    for (int j = 0; j < 64; j++) {
        float xv = xn[j];
        aq += qw[o * 64 + j] * xv;
        ak += kw[o * 64 + j] * xv;
        av += vw[o * 64 + j] * xv;
    }
    int off = (b * TG2 + cell) * CC + o;
    g_qg[off] = aq; g_kg[off] = ak; g_vg[off] = av;
}

// ---------------- K4: full-res GN + q/k/v convs (128-pixel tiles, f4 LDS) ---------
__global__ __launch_bounds__(256) void k_qkv(const float* __restrict__ x,
                                             const float* __restrict__ gnw, const float* __restrict__ gnb,
                                             const float* __restrict__ W0, const float* __restrict__ B0,
                                             const float* __restrict__ W1, const float* __restrict__ B1,
                                             const float* __restrict__ W2, const float* __restrict__ B2) {
    __shared__ float sXn[64 * 128];      // [c][p]
    __shared__ float sWt[64 * 64];       // [c][o]  (transposed)
    __shared__ float sB[64];
    int b = blockIdx.y;
    int pix0 = blockIdx.x * 128;
    int t = threadIdx.x;
    float mean = g_stats[b * 2] * (1.f / (float)NPB);
    float inv  = rsqrtf(g_stats[b * 2 + 1] * (1.f / (float)NPB) - mean * mean + EPSV);

    for (int i = t; i < 2048; i += 256) {        // f4 index: c = i>>5, p4 = i&31
        int c = i >> 5, p4 = i & 31;
        float4 v = *(const float4*)(x + ((size_t)b * CC + c) * HW + pix0 + p4 * 4);
        float gw = gnw[c], gb = gnb[c];
        v.x = (v.x - mean) * inv * gw + gb;
        v.y = (v.y - mean) * inv * gw + gb;
        v.z = (v.z - mean) * inv * gw + gb;
        v.w = (v.w - mean) * inv * gw + gb;
        *(float4*)(sXn + c * 128 + p4 * 4) = v;
    }
    const float* Ws[3] = {W0, W1, W2};
    const float* Bs[3] = {B0, B1, B2};
    float* Os[3] = {g_q, g_k, g_v};
    int og = t >> 4, pg = t & 15;                // 16 o-groups(4) x 16 p-groups(8)

    for (int m = 0; m < 3; m++) {
        __syncthreads();
        for (int i = t; i < 1024; i += 256) {    // f4 of W: o = i>>4, c4 = i&15
            int o = i >> 4, c4 = i & 15;
            float4 w = *(const float4*)(Ws[m] + o * 64 + c4 * 4);
            sWt[(c4 * 4 + 0) * 64 + o] = w.x;
            sWt[(c4 * 4 + 1) * 64 + o] = w.y;
            sWt[(c4 * 4 + 2) * 64 + o] = w.z;
            sWt[(c4 * 4 + 3) * 64 + o] = w.w;
        }
        if (t < 64) sB[t] = Bs[m][t];
        __syncthreads();
        float acc[4][8];
#pragma unroll
        for (int j = 0; j < 4; j++) {
            float bb = sB[og * 4 + j];
#pragma unroll
            for (int p = 0; p < 8; p++) acc[j][p] = bb;
        }
#pragma unroll 4
        for (int c = 0; c < 64; c++) {
            float4 x0 = *(const float4*)(sXn + c * 128 + pg * 8);
            float4 x1 = *(const float4*)(sXn + c * 128 + pg * 8 + 4);
            float4 w = *(const float4*)(sWt + c * 64 + og * 4);
            float wj[4] = {w.x, w.y, w.z, w.w};
#pragma unroll
            for (int j = 0; j < 4; j++) {
                acc[j][0] += wj[j] * x0.x; acc[j][1] += wj[j] * x0.y;
                acc[j][2] += wj[j] * x0.z; acc[j][3] += wj[j] * x0.w;
                acc[j][4] += wj[j] * x1.x; acc[j][5] += wj[j] * x1.y;
                acc[j][6] += wj[j] * x1.z; acc[j][7] += wj[j] * x1.w;
            }
        }
        float* O = Os[m];
#pragma unroll
        for (int j = 0; j < 4; j++) {
            int o = og * 4 + j;
            size_t base = ((size_t)b * CC + o) * HW + pix0 + pg * 8;
            *(float4*)(O + base)     = make_float4(acc[j][0], acc[j][1], acc[j][2], acc[j][3]);
            *(float4*)(O + base + 4) = make_float4(acc[j][4], acc[j][5], acc[j][6], acc[j][7]);
        }
    }
}

// ---------------- K5: wm split-K GEMM (K-step 16, f4 global loads) ----------------
__global__ __launch_bounds__(784, 1) void k_wm() {
    int b = blockIdx.y, kb = blockIdx.x;
    int s0 = kb * KCHUNK;
    int send = min(s0 + KCHUNK, SPB);
    const float* Q = g_q + (size_t)b * NPB;
    const float* K = g_k + (size_t)b * NPB;
    __shared__ float qs[16][196];
    __shared__ float ks[16][196];
    int t = threadIdx.x;
    int ty = t / 28, tx = t - ty * 28;
    float acc[7][7];
#pragma unroll
    for (int i = 0; i < 7; i++)
#pragma unroll
        for (int j = 0; j < 7; j++) acc[i][j] = 0.f;

    for (int st = s0; st < send; st += 16) {
        __syncthreads();
        {
            int r = t / 49, c4 = t - (t / 49) * 49;   // 784 f4 each
            int s = st + r;
            float4 qv = make_float4(0.f, 0.f, 0.f, 0.f), kv = qv;
            if (s < send) {
                qv = *(const float4*)(Q + (size_t)s * 196 + c4 * 4);
                kv = *(const float4*)(K + (size_t)s * 196 + c4 * 4);
            }
            *(float4*)&qs[r][c4 * 4] = qv;
            *(float4*)&ks[r][c4 * 4] = kv;
        }
        __syncthreads();
#pragma unroll 4
        for (int ss = 0; ss < 16; ss++) {
            float q7[7], k7[7];
#pragma unroll
            for (int i = 0; i < 7; i++) {
                q7[i] = qs[ss][ty * 7 + i];
                k7[i] = ks[ss][tx * 7 + i];
            }
#pragma unroll
            for (int i = 0; i < 7; i++)
#pragma unroll
                for (int j = 0; j < 7; j++) acc[i][j] += q7[i] * k7[j];
        }
    }
    float* out = g_wmp + ((size_t)b * GRIDK + kb) * (P2 * P2);
#pragma unroll
    for (int i = 0; i < 7; i++)
#pragma unroll
        for (int j = 0; j < 7; j++)
            out[(ty * 7 + i) * P2 + tx * 7 + j] = acc[i][j];
}

// ---------------- K6: reduce wm partials + softmax + write wm^T ----------------
__global__ void k_softmax_wm() {
    int b = blockIdx.y, p = blockIdx.x, t = threadIdx.x;
    __shared__ float red[256];
    float v = -3.0e38f;
    if (t < P2) {
        float s = 0.f;
        for (int r = 0; r < GRIDK; r++)
            s += g_wmp[((size_t)(b * GRIDK + r)) * (P2 * P2) + p * P2 + t];
        v = s * (1.f / 256.f);
    }
    red[t] = v;
    __syncthreads();
    for (int o = 128; o > 0; o >>= 1) {
        if (t < o) red[t] = fmaxf(red[t], red[t + o]);
        __syncthreads();
    }
    float mx = red[0];
    __syncthreads();
    float e = (t < P2) ? __expf(v - mx) : 0.f;
    red[t] = e;
    __syncthreads();
    for (int o = 128; o > 0; o >>= 1) {
        if (t < o) red[t] += red[t + o];
        __syncthreads();
    }
    float inv = 1.f / red[0];
    if (t < P2) g_wmT[(b * P2 + t) * P2 + p] = e * inv;   // transposed: [k][q]
}

// ---------------- K7: wg[p][q] = qg[p].kg[q]/8  (transposed smem, f4 LDS) -------
__global__ __launch_bounds__(256) void k_wg() {
    int b = blockIdx.z;
    int p0 = blockIdx.y * 64, q0 = blockIdx.x * 64;
    __shared__ float Qs[64][64];   // [c][row]
    __shared__ float Ks[64][64];
    const float* Qg = g_qg + (size_t)b * TG2 * CC;
    const float* Kg = g_kg + (size_t)b * TG2 * CC;
    int t = threadIdx.x;
    for (int i = t; i < 1024; i += 256) {         // f4: r = i>>4, c4 = i&15
        int r = i >> 4, c4 = i & 15;
        float4 q4 = *(const float4*)(Qg + (p0 + r) * 64 + c4 * 4);
        float4 k4 = *(const float4*)(Kg + (q0 + r) * 64 + c4 * 4);
        Qs[c4 * 4 + 0][r] = q4.x; Qs[c4 * 4 + 1][r] = q4.y;
        Qs[c4 * 4 + 2][r] = q4.z; Qs[c4 * 4 + 3][r] = q4.w;
        Ks[c4 * 4 + 0][r] = k4.x; Ks[c4 * 4 + 1][r] = k4.y;
        Ks[c4 * 4 + 2][r] = k4.z; Ks[c4 * 4 + 3][r] = k4.w;
    }
    __syncthreads();
    int ty = t >> 4, tx = t & 15;
    float acc[4][4];
#pragma unroll
    for (int i = 0; i < 4; i++)
#pragma unroll
        for (int j = 0; j < 4; j++) acc[i][j] = 0.f;
#pragma unroll 8
    for (int c = 0; c < 64; c++) {
        float4 a4 = *(const float4*)&Qs[c][ty * 4];
        float4 b4 = *(const float4*)&Ks[c][tx * 4];
        float a[4] = {a4.x, a4.y, a4.z, a4.w};
        float bb[4] = {b4.x, b4.y, b4.z, b4.w};
#pragma unroll
        for (int i = 0; i < 4; i++)
#pragma unroll
            for (int j = 0; j < 4; j++) acc[i][j] += a[i] * bb[j];
    }
    float* out = g_wg + (size_t)b * TG2 * TG2;
#pragma unroll
    for (int i = 0; i < 4; i++) {
        float4 r = make_float4(acc[i][0] * 0.125f, acc[i][1] * 0.125f,
                               acc[i][2] * 0.125f, acc[i][3] * 0.125f);
        *(float4*)(out + (size_t)(p0 + ty * 4 + i) * TG2 + q0 + tx * 4) = r;
    }
}

// ---------------- K8: softmax over wg rows (f4) ----------------
__global__ void k_softmax_wg() {
    int b = blockIdx.y, p = blockIdx.x, t = threadIdx.x;
    float* row = g_wg + ((size_t)b * TG2 + p) * TG2;
    __shared__ float sv[TG2];
    __shared__ float red[256];
    float lm = -3.0e38f;
    for (int i = t; i < 784; i += 256) {
        float4 v = *(const float4*)(row + i * 4);
        *(float4*)(sv + i * 4) = v;
        lm = fmaxf(lm, fmaxf(fmaxf(v.x, v.y), fmaxf(v.z, v.w)));
    }
    red[t] = lm;
    __syncthreads();
    for (int o = 128; o > 0; o >>= 1) {
        if (t < o) red[t] = fmaxf(red[t], red[t + o]);
        __syncthreads();
    }
    float mx = red[0];
    __syncthreads();
    float ls = 0.f;
    for (int i = t; i < 784; i += 256) {
        float4 v = *(const float4*)(sv + i * 4);
        v.x = __expf(v.x - mx); v.y = __expf(v.y - mx);
        v.z = __expf(v.z - mx); v.w = __expf(v.w - mx);
        *(float4*)(sv + i * 4) = v;
        ls += v.x + v.y + v.z + v.w;
    }
    red[t] = ls;
    __syncthreads();
    for (int o = 128; o > 0; o >>= 1) {
        if (t < o) red[t] += red[t + o];
        __syncthreads();
    }
    float inv = 1.f / red[0];
    for (int i = t; i < 784; i += 256) {
        float4 v = *(const float4*)(sv + i * 4);
        v.x *= inv; v.y *= inv; v.z *= inv; v.w *= inv;
        *(float4*)(row + i * 4) = v;
    }
}

// ---------------- K9: hg[q][c] = sum_k wg[q][k]*vg[k][c] (transposed Ws) --------
__global__ __launch_bounds__(256) void k_hg() {
    int b = blockIdx.y;
    int q0 = blockIdx.x * 64;
    __shared__ float Ws[32][64];   // [kk][row]
    __shared__ float Vs[32][64];   // [kk][c]
    const float* Wg = g_wg + (size_t)b * TG2 * TG2;
    const float* Vg = g_vg + (size_t)b * TG2 * CC;
    int t = threadIdx.x;
    int ty = t >> 4, tx = t & 15;
    float acc[4][4];
#pragma unroll
    for (int i = 0; i < 4; i++)
#pragma unroll
        for (int j = 0; j < 4; j++) acc[i][j] = 0.f;

    for (int k0 = 0; k0 < TG2; k0 += 32) {
        __syncthreads();
        for (int i = t; i < 512; i += 256) {      // Ws: r = i>>3, k4 = i&7
            int r = i >> 3, k4 = i & 7;
            float4 w4 = *(const float4*)(Wg + (size_t)(q0 + r) * TG2 + k0 + k4 * 4);
            Ws[k4 * 4 + 0][r] = w4.x; Ws[k4 * 4 + 1][r] = w4.y;
            Ws[k4 * 4 + 2][r] = w4.z; Ws[k4 * 4 + 3][r] = w4.w;
        }
        for (int i = t; i < 512; i += 256) {      // Vs: kk = i>>4, c4 = i&15
            int kk = i >> 4, c4 = i & 15;
            *(float4*)&Vs[kk][c4 * 4] = *(const float4*)(Vg + (k0 + kk) * 64 + c4 * 4);
        }
        __syncthreads();
#pragma unroll 8
        for (int kk = 0; kk < 32; kk++) {
            float4 a4 = *(const float4*)&Ws[kk][ty * 4];
            float4 b4 = *(const float4*)&Vs[kk][tx * 4];
            float a[4] = {a4.x, a4.y, a4.z, a4.w};
            float bb[4] = {b4.x, b4.y, b4.z, b4.w};
#pragma unroll
            for (int i = 0; i < 4; i++)
#pragma unroll
                for (int j = 0; j < 4; j++) acc[i][j] += a[i] * bb[j];
        }
    }
#pragma unroll
    for (int i = 0; i < 4; i++)
        *(float4*)(g_hg + (size_t)(b * TG2 + q0 + ty * 4 + i) * 64 + tx * 4) =
            make_float4(acc[i][0], acc[i][1], acc[i][2], acc[i][3]);
}

// ---------------- K10: hp[s][q] = sum_k v[s][k]*wmT[k][q]  (8x7 tiles) ----------
__global__ __launch_bounds__(224) void k_hp() {
    int b = blockIdx.y;
    int s0 = blockIdx.x * 64;
    __shared__ float As[28][64];    // [kk][row]  (transposed V tile)
    __shared__ float Bs[28][196];   // [kk][q]
    const float* V   = g_v   + (size_t)b * NPB;
    const float* WMT = g_wmT + (size_t)b * P2 * P2;
    int t = threadIdx.x;
    int rg = t / 28, cg = t - (t / 28) * 28;   // rg 0..7 (8 rows), cg 0..27 (7 cols)
    float acc[8][7];
#pragma unroll
    for (int i = 0; i < 8; i++)
#pragma unroll
        for (int j = 0; j < 7; j++) acc[i][j] = 0.f;

    for (int k0 = 0; k0 < 196; k0 += 28) {
        __syncthreads();
        for (int i = t; i < 448; i += 224) {       // As: r = i/7, k4 = i%7
            int r = i / 7, k4 = i - (i / 7) * 7;
            float4 vv = *(const float4*)(V + (size_t)(s0 + r) * 196 + k0 + k4 * 4);
            As[k4 * 4 + 0][r] = vv.x; As[k4 * 4 + 1][r] = vv.y;
            As[k4 * 4 + 2][r] = vv.z; As[k4 * 4 + 3][r] = vv.w;
        }
        for (int i = t; i < 1372; i += 224) {      // Bs: kk = i/49, c4 = i%49
            int kk = i / 49, c4 = i - (i / 49) * 49;
            *(float4*)&Bs[kk][c4 * 4] = *(const float4*)(WMT + (size_t)(k0 + kk) * 196 + c4 * 4);
        }
        __syncthreads();
#pragma unroll 4
        for (int kk = 0; kk < 28; kk++) {
            float4 a0 = *(const float4*)&As[kk][rg * 8];
            float4 a1 = *(const float4*)&As[kk][rg * 8 + 4];
            float a[8] = {a0.x, a0.y, a0.z, a0.w, a1.x, a1.y, a1.z, a1.w};
            float b7[7];
#pragma unroll
            for (int j = 0; j < 7; j++) b7[j] = Bs[kk][cg * 7 + j];
#pragma unroll
            for (int i = 0; i < 8; i++)
#pragma unroll
                for (int j = 0; j < 7; j++) acc[i][j] += a[i] * b7[j];
        }
    }
    float* O = g_hin + (size_t)b * NPB;
#pragma unroll
    for (int i = 0; i < 8; i++)
#pragma unroll
        for (int j = 0; j < 7; j++)
            O[(size_t)(s0 + rg * 8 + i) * 196 + cg * 7 + j] = acc[i][j];
}

// ---------------- K11: proj fused blend + conv + residual (128-pixel tiles) -----
__global__ __launch_bounds__(256) void k_proj(const float* __restrict__ x,
                                              const float* __restrict__ pw,
                                              float* __restrict__ out) {
    __shared__ float sH[64 * 128];    // [c][p]
    __shared__ float sWt[64 * 64];    // [c][o]
    int b = blockIdx.y;
    int pix0 = blockIdx.x * 128;
    int t = threadIdx.x;

    for (int i = t; i < 2048; i += 256) {     // f4: c = i>>5, p4 = i&31
        int c = i >> 5, p4 = i & 31;
        int pgl = pix0 + p4 * 4;
        int h = pgl / WID, w = pgl - h * WID;
        int cell = (h >> 3) * 56 + (w >> 3);  // 4 consecutive pixels share one cell
        float4 hp = *(const float4*)(g_hin + (size_t)b * NPB + (size_t)c * HW + pgl);
        float hg = g_hg[(size_t)(b * TG2 + cell) * 64 + c] * 0.25f;
        float4 r = make_float4(0.75f * hp.x + hg, 0.75f * hp.y + hg,
                               0.75f * hp.z + hg, 0.75f * hp.w + hg);
        *(float4*)(sH + c * 128 + p4 * 4) = r;
    }
    for (int i = t; i < 1024; i += 256) {     // f4 of W: o = i>>4, c4 = i&15
        int o = i >> 4, c4 = i & 15;
        float4 w = *(const float4*)(pw + o * 64 + c4 * 4);
        sWt[(c4 * 4 + 0) * 64 + o] = w.x;
        sWt[(c4 * 4 + 1) * 64 + o] = w.y;
        sWt[(c4 * 4 + 2) * 64 + o] = w.z;
        sWt[(c4 * 4 + 3) * 64 + o] = w.w;
    }
    __syncthreads();

    int og = t >> 4, pg = t & 15;
    float acc[4][8];
#pragma unroll
    for (int j = 0; j < 4; j++)
#pragma unroll
        for (int p = 0; p < 8; p++) acc[j][p] = 0.f;
#pragma unroll 4
    for (int c = 0; c < 64; c++) {
        float4 x0 = *(const float4*)(sH + c * 128 + pg * 8);
        float4 x1 = *(const float4*)(sH + c * 128 + pg * 8 + 4);
        float4 w = *(const float4*)(sWt + c * 64 + og * 4);
        float wj[4] = {w.x, w.y, w.z, w.w};
#pragma unroll
        for (int j = 0; j < 4; j++) {
            acc[j][0] += wj[j] * x0.x; acc[j][1] += wj[j] * x0.y;
            acc[j][2] += wj[j] * x0.z; acc[j][3] += wj[j] * x0.w;
            acc[j][4] += wj[j] * x1.x; acc[j][5] += wj[j] * x1.y;
            acc[j][6] += wj[j] * x1.z; acc[j][7] += wj[j] * x1.w;
        }
    }
#pragma unroll
    for (int j = 0; j < 4; j++) {
        int o = og * 4 + j;
        size_t base = ((size_t)b * CC + o) * HW + pix0 + pg * 8;
        float4 xr0 = *(const float4*)(x + base);
        float4 xr1 = *(const float4*)(x + base + 4);
        *(float4*)(out + base) = make_float4(acc[j][0] + xr0.x, acc[j][1] + xr0.y,
                                             acc[j][2] + xr0.z, acc[j][3] + xr0.w);
        *(float4*)(out + base + 4) = make_float4(acc[j][4] + xr1.x, acc[j][5] + xr1.y,
                                                 acc[j][6] + xr1.z, acc[j][7] + xr1.w);
    }
}

extern "C" void kernel_launch(void* const* d_in, const int* in_sizes, int n_in,
                              void* d_out, int out_size) {
    const float* x   = (const float*)d_in[0];
    const float* gnw = (const float*)d_in[1];
    const float* gnb = (const float*)d_in[2];
    const float* qw  = (const float*)d_in[3];
    const float* qb  = (const float*)d_in[4];
    const float* kw  = (const float*)d_in[5];
    const float* kb  = (const float*)d_in[6];
    const float* vw  = (const float*)d_in[7];
    const float* vb  = (const float*)d_in[8];
    const float* pw  = (const float*)d_in[9];
    float* out = (float*)d_out;

    k_pool_stats<<<dim3(784, BATCH), 256>>>(x);
    k_stats2<<<BATCH, 256>>>();
    k_qkvg<<<dim3(TG2, BATCH), 64>>>(gnw, gnb, qw, qb, kw, kb, vw, vb);
    k_qkv<<<dim3(HW / 128, BATCH), 256>>>(x, gnw, gnb, qw, qb, kw, kb, vw, vb);
    k_wm<<<dim3(GRIDK, BATCH), 784>>>();
    k_softmax_wm<<<dim3(P2, BATCH), 256>>>();
    k_wg<<<dim3(TG2 / 64, TG2 / 64, BATCH), 256>>>();
    k_softmax_wg<<<dim3(TG2, BATCH), 256>>>();
    k_hg<<<dim3(TG2 / 64, BATCH), 256>>>();
    k_hp<<<dim3(SPB / 64, BATCH), 224>>>();
    k_proj<<<dim3(HW / 128, BATCH), 256>>>(x, pw, out);
}

// round 7
// speedup vs baseline: 1.1344x; 1.1134x over previous
#include <cuda_runtime.h>

#define HW      200704          // 448*448
#define WID     448
#define CC      64
#define BATCH   2
#define TG2     3136            // 56*56
#define P2      196
#define NPB     12845056        // C*HW per batch
#define SPB     65536           // S per batch
#define EPSV    1e-5f
#define GRIDK   74
#define KCHUNK  886             // ceil(65536/74)

// ---------------- scratch ----------------
__device__ float g_q[BATCH * NPB];
__device__ float g_k[BATCH * NPB];
__device__ float g_v[BATCH * NPB];
__device__ float g_hin[BATCH * NPB];
__device__ float g_spart[BATCH * 784 * 2];
__device__ float g_stats[BATCH * 2];
__device__ float g_px[BATCH * CC * TG2];
__device__ float g_qg[BATCH * TG2 * CC];
__device__ float g_kg[BATCH * TG2 * CC];
__device__ float g_vg[BATCH * TG2 * CC];
__device__ float g_wmp[BATCH * GRIDK * P2 * P2];
__device__ float g_wmT[BATCH * P2 * P2];     // wmT[k][q]
__device__ float g_wg[(size_t)BATCH * TG2 * TG2];
__device__ float g_hg[BATCH * TG2 * CC];

// ---------------- K1: 8x8 avg-pool of x + GN stat partials ----------------
__global__ __launch_bounds__(256) void k_pool_stats(const float* __restrict__ x) {
    int b = blockIdx.y;
    int idx = blockIdx.x * 256 + threadIdx.x;
    int c = idx / TG2;
    int cell = idx - c * TG2;
    int th = cell / 56, tw = cell - th * 56;
    const float* xp = x + ((size_t)b * CC + c) * HW + (size_t)(th * 8) * WID + tw * 8;
    float s = 0.f, s2 = 0.f;
#pragma unroll
    for (int r = 0; r < 8; r++) {
        float4 a = *(const float4*)(xp + r * WID);
        float4 bb = *(const float4*)(xp + r * WID + 4);
        s  += a.x + a.y + a.z + a.w + bb.x + bb.y + bb.z + bb.w;
        s2 += a.x*a.x + a.y*a.y + a.z*a.z + a.w*a.w
            + bb.x*bb.x + bb.y*bb.y + bb.z*bb.z + bb.w*bb.w;
    }
    g_px[(b * CC + c) * TG2 + cell] = s * (1.f / 64.f);

    __shared__ float r0[256], r1[256];
    int t = threadIdx.x;
    r0[t] = s; r1[t] = s2;
    __syncthreads();
    for (int o = 128; o > 0; o >>= 1) {
        if (t < o) { r0[t] += r0[t + o]; r1[t] += r1[t + o]; }
        __syncthreads();
    }
    if (t == 0) {
        g_spart[(b * 784 + blockIdx.x) * 2 + 0] = r0[0];
        g_spart[(b * 784 + blockIdx.x) * 2 + 1] = r1[0];
    }
}

// ---------------- K2: reduce stat partials ----------------
__global__ void k_stats2() {
    int b = blockIdx.x, t = threadIdx.x;
    float s = 0.f, s2 = 0.f;
    for (int i = t; i < 784; i += 256) {
        s  += g_spart[(b * 784 + i) * 2 + 0];
        s2 += g_spart[(b * 784 + i) * 2 + 1];
    }
    __shared__ float r0[256], r1[256];
    r0[t] = s; r1[t] = s2;
    __syncthreads();
    for (int o = 128; o > 0; o >>= 1) {
        if (t < o) { r0[t] += r0[t + o]; r1[t] += r1[t + o]; }
        __syncthreads();
    }
    if (t == 0) { g_stats[b * 2] = r0[0]; g_stats[b * 2 + 1] = r1[0]; }
}

// ---------------- K3: pooled qkv from pooled x ----------------
__global__ void k_qkvg(const float* __restrict__ gnw, const float* __restrict__ gnb,
                       const float* __restrict__ qw, const float* __restrict__ qb,
                       const float* __restrict__ kw, const float* __restrict__ kb,
                       const float* __restrict__ vw, const float* __restrict__ vb) {
    int b = blockIdx.y, cell = blockIdx.x, o = threadIdx.x;
    float mean = g_stats[b * 2] * (1.f / (float)NPB);
    float var  = g_stats[b * 2 + 1] * (1.f / (float)NPB) - mean * mean;
    float inv  = rsqrtf(var + EPSV);
    __shared__ float xn[64];
    xn[o] = (g_px[(b * CC + o) * TG2 + cell] - mean) * inv * gnw[o] + gnb[o];
    __syncthreads();
    float aq = qb[o], ak = kb[o], av = vb[o];
#pragma unroll 8
    for (int j = 0; j < 64; j++) {
        float xv = xn[j];
        aq += qw[o * 64 + j] * xv;
        ak += kw[o * 64 + j] * xv;
        av += vw[o * 64 + j] * xv;
    }
    int off = (b * TG2 + cell) * CC + o;
    g_qg[off] = aq; g_kg[off] = ak; g_vg[off] = av;
}

// ---------------- K4: GN + q/k/v convs, 8x8 register blocking, conflict-free ----
__global__ __launch_bounds__(128) void k_qkv(const float* __restrict__ x,
                                             const float* __restrict__ gnw, const float* __restrict__ gnb,
                                             const float* __restrict__ W0, const float* __restrict__ B0,
                                             const float* __restrict__ W1, const float* __restrict__ B1,
                                             const float* __restrict__ W2, const float* __restrict__ B2) {
    __shared__ float sXn[64][128];       // [c][p]
    __shared__ float sWt[64][64];        // [c][o]
    __shared__ float sB[64];
    int b = blockIdx.y;
    int pix0 = blockIdx.x * 128;
    int t = threadIdx.x;
    float mean = g_stats[b * 2] * (1.f / (float)NPB);
    float inv  = rsqrtf(g_stats[b * 2 + 1] * (1.f / (float)NPB) - mean * mean + EPSV);

    for (int i = t; i < 2048; i += 128) {        // c = i>>5, p4 = i&31
        int c = i >> 5, p4 = i & 31;
        float4 v = *(const float4*)(x + ((size_t)b * CC + c) * HW + pix0 + p4 * 4);
        float gw = gnw[c] * inv, gb = gnb[c] - mean * gnw[c] * inv;
        v.x = v.x * gw + gb; v.y = v.y * gw + gb;
        v.z = v.z * gw + gb; v.w = v.w * gw + gb;
        *(float4*)&sXn[c][p4 * 4] = v;
    }
    const float* Ws[3] = {W0, W1, W2};
    const float* Bs[3] = {B0, B1, B2};
    float* Os[3] = {g_q, g_k, g_v};
    int og = t >> 4;     // 0..7  (8 channel groups)
    int pg = t & 15;     // 0..15 (16 pixel groups)

    for (int m = 0; m < 3; m++) {
        __syncthreads();
        for (int i = t; i < 1024; i += 128) {    // o = i&63, c4 = i>>6 (STS conflict-free)
            int o = i & 63, c4 = i >> 6;
            float4 w = *(const float4*)(Ws[m] + o * 64 + c4 * 4);
            sWt[c4 * 4 + 0][o] = w.x;
            sWt[c4 * 4 + 1][o] = w.y;
            sWt[c4 * 4 + 2][o] = w.z;
            sWt[c4 * 4 + 3][o] = w.w;
        }
        if (t < 64) sB[t] = Bs[m][t];
        __syncthreads();

        float acc[8][8];
#pragma unroll
        for (int i = 0; i < 8; i++)
#pragma unroll
            for (int j = 0; j < 8; j++) acc[i][j] = 0.f;

#pragma unroll 8
        for (int c = 0; c < 64; c++) {
            float4 x0 = *(const float4*)&sXn[c][pg * 4];        // phase-consecutive
            float4 x1 = *(const float4*)&sXn[c][pg * 4 + 64];
            float4 w0 = *(const float4*)&sWt[c][og * 4];        // phase-broadcast
            float4 w1 = *(const float4*)&sWt[c][og * 4 + 32];
            float a[8] = {w0.x, w0.y, w0.z, w0.w, w1.x, w1.y, w1.z, w1.w};
            float p[8] = {x0.x, x0.y, x0.z, x0.w, x1.x, x1.y, x1.z, x1.w};
#pragma unroll
            for (int i = 0; i < 8; i++)
#pragma unroll
                for (int j = 0; j < 8; j++) acc[i][j] += a[i] * p[j];
        }
        float* O = Os[m];
#pragma unroll
        for (int i = 0; i < 8; i++) {
            int o = og * 4 + ((i < 4) ? i : 28 + i);
            float bb = sB[o];
            size_t base = ((size_t)b * CC + o) * HW + pix0;
            *(float4*)(O + base + pg * 4) =
                make_float4(acc[i][0] + bb, acc[i][1] + bb, acc[i][2] + bb, acc[i][3] + bb);
            *(float4*)(O + base + 64 + pg * 4) =
                make_float4(acc[i][4] + bb, acc[i][5] + bb, acc[i][6] + bb, acc[i][7] + bb);
        }
    }
}

// ---------------- K5: wm split-K GEMM ----------------
__global__ __launch_bounds__(784, 1) void k_wm() {
    int b = blockIdx.y, kb = blockIdx.x;
    int s0 = kb * KCHUNK;
    int send = min(s0 + KCHUNK, SPB);
    const float* Q = g_q + (size_t)b * NPB;
    const float* K = g_k + (size_t)b * NPB;
    __shared__ float qs[16][196];
    __shared__ float ks[16][196];
    int t = threadIdx.x;
    int ty = t / 28, tx = t - ty * 28;
    float acc[7][7];
#pragma unroll
    for (int i = 0; i < 7; i++)
#pragma unroll
        for (int j = 0; j < 7; j++) acc[i][j] = 0.f;

    for (int st = s0; st < send; st += 16) {
        __syncthreads();
        {
            int r = t / 49, c4 = t - (t / 49) * 49;
            int s = st + r;
            float4 qv = make_float4(0.f, 0.f, 0.f, 0.f), kv = qv;
            if (s < send) {
                qv = *(const float4*)(Q + (size_t)s * 196 + c4 * 4);
                kv = *(const float4*)(K + (size_t)s * 196 + c4 * 4);
            }
            *(float4*)&qs[r][c4 * 4] = qv;
            *(float4*)&ks[r][c4 * 4] = kv;
        }
        __syncthreads();
#pragma unroll 4
        for (int ss = 0; ss < 16; ss++) {
            float q7[7], k7[7];
#pragma unroll
            for (int i = 0; i < 7; i++) {
                q7[i] = qs[ss][ty * 7 + i];
                k7[i] = ks[ss][tx * 7 + i];
            }
#pragma unroll
            for (int i = 0; i < 7; i++)
#pragma unroll
                for (int j = 0; j < 7; j++) acc[i][j] += q7[i] * k7[j];
        }
    }
    float* out = g_wmp + ((size_t)b * GRIDK + kb) * (P2 * P2);
#pragma unroll
    for (int i = 0; i < 7; i++)
#pragma unroll
        for (int j = 0; j < 7; j++)
            out[(ty * 7 + i) * P2 + tx * 7 + j] = acc[i][j];
}

// ---------------- K6: reduce wm partials + softmax + write wm^T ----------------
__global__ void k_softmax_wm() {
    int b = blockIdx.y, p = blockIdx.x, t = threadIdx.x;
    __shared__ float red[256];
    float v = -3.0e38f;
    if (t < P2) {
        float s = 0.f;
        for (int r = 0; r < GRIDK; r++)
            s += g_wmp[((size_t)(b * GRIDK + r)) * (P2 * P2) + p * P2 + t];
        v = s * (1.f / 256.f);
    }
    red[t] = v;
    __syncthreads();
    for (int o = 128; o > 0; o >>= 1) {
        if (t < o) red[t] = fmaxf(red[t], red[t + o]);
        __syncthreads();
    }
    float mx = red[0];
    __syncthreads();
    float e = (t < P2) ? __expf(v - mx) : 0.f;
    red[t] = e;
    __syncthreads();
    for (int o = 128; o > 0; o >>= 1) {
        if (t < o) red[t] += red[t + o];
        __syncthreads();
    }
    float inv = 1.f / red[0];
    if (t < P2) g_wmT[(b * P2 + t) * P2 + p] = e * inv;
}

// ---------------- K7: wg[p][q] = qg[p].kg[q]/8 ----------------
__global__ __launch_bounds__(256) void k_wg() {
    int b = blockIdx.z;
    int p0 = blockIdx.y * 64, q0 = blockIdx.x * 64;
    __shared__ float Qs[64][64];
    __shared__ float Ks[64][64];
    const float* Qg = g_qg + (size_t)b * TG2 * CC;
    const float* Kg = g_kg + (size_t)b * TG2 * CC;
    int t = threadIdx.x;
    for (int i = t; i < 1024; i += 256) {
        int r = i >> 4, c4 = i & 15;
        float4 q4 = *(const float4*)(Qg + (p0 + r) * 64 + c4 * 4);
        float4 k4 = *(const float4*)(Kg + (q0 + r) * 64 + c4 * 4);
        Qs[c4 * 4 + 0][r] = q4.x; Qs[c4 * 4 + 1][r] = q4.y;
        Qs[c4 * 4 + 2][r] = q4.z; Qs[c4 * 4 + 3][r] = q4.w;
        Ks[c4 * 4 + 0][r] = k4.x; Ks[c4 * 4 + 1][r] = k4.y;
        Ks[c4 * 4 + 2][r] = k4.z; Ks[c4 * 4 + 3][r] = k4.w;
    }
    __syncthreads();
    int ty = t >> 4, tx = t & 15;
    float acc[4][4];
#pragma unroll
    for (int i = 0; i < 4; i++)
#pragma unroll
        for (int j = 0; j < 4; j++) acc[i][j] = 0.f;
#pragma unroll 8
    for (int c = 0; c < 64; c++) {
        float4 a4 = *(const float4*)&Qs[c][ty * 4];
        float4 b4 = *(const float4*)&Ks[c][tx * 4];
        float a[4] = {a4.x, a4.y, a4.z, a4.w};
        float bb[4] = {b4.x, b4.y, b4.z, b4.w};
#pragma unroll
        for (int i = 0; i < 4; i++)
#pragma unroll
            for (int j = 0; j < 4; j++) acc[i][j] += a[i] * bb[j];
    }
    float* out = g_wg + (size_t)b * TG2 * TG2;
#pragma unroll
    for (int i = 0; i < 4; i++) {
        float4 r = make_float4(acc[i][0] * 0.125f, acc[i][1] * 0.125f,
                               acc[i][2] * 0.125f, acc[i][3] * 0.125f);
        *(float4*)(out + (size_t)(p0 + ty * 4 + i) * TG2 + q0 + tx * 4) = r;
    }
}

// ---------------- K8: softmax over wg rows ----------------
__global__ void k_softmax_wg() {
    int b = blockIdx.y, p = blockIdx.x, t = threadIdx.x;
    float* row = g_wg + ((size_t)b * TG2 + p) * TG2;
    __shared__ float sv[TG2];
    __shared__ float red[256];
    float lm = -3.0e38f;
    for (int i = t; i < 784; i += 256) {
        float4 v = *(const float4*)(row + i * 4);
        *(float4*)(sv + i * 4) = v;
        lm = fmaxf(lm, fmaxf(fmaxf(v.x, v.y), fmaxf(v.z, v.w)));
    }
    red[t] = lm;
    __syncthreads();
    for (int o = 128; o > 0; o >>= 1) {
        if (t < o) red[t] = fmaxf(red[t], red[t + o]);
        __syncthreads();
    }
    float mx = red[0];
    __syncthreads();
    float ls = 0.f;
    for (int i = t; i < 784; i += 256) {
        float4 v = *(const float4*)(sv + i * 4);
        v.x = __expf(v.x - mx); v.y = __expf(v.y - mx);
        v.z = __expf(v.z - mx); v.w = __expf(v.w - mx);
        *(float4*)(sv + i * 4) = v;
        ls += v.x + v.y + v.z + v.w;
    }
    red[t] = ls;
    __syncthreads();
    for (int o = 128; o > 0; o >>= 1) {
        if (t < o) red[t] += red[t + o];
        __syncthreads();
    }
    float inv = 1.f / red[0];
    for (int i = t; i < 784; i += 256) {
        float4 v = *(const float4*)(sv + i * 4);
        v.x *= inv; v.y *= inv; v.z *= inv; v.w *= inv;
        *(float4*)(row + i * 4) = v;
    }
}

// ---------------- K9: hg[q][c] = sum_k wg[q][k]*vg[k][c] ----------------
__global__ __launch_bounds__(256) void k_hg() {
    int b = blockIdx.y;
    int q0 = blockIdx.x * 64;
    __shared__ float Ws[32][64];
    __shared__ float Vs[32][64];
    const float* Wg = g_wg + (size_t)b * TG2 * TG2;
    const float* Vg = g_vg + (size_t)b * TG2 * CC;
    int t = threadIdx.x;
    int ty = t >> 4, tx = t & 15;
    float acc[4][4];
#pragma unroll
    for (int i = 0; i < 4; i++)
#pragma unroll
        for (int j = 0; j < 4; j++) acc[i][j] = 0.f;

    for (int k0 = 0; k0 < TG2; k0 += 32) {
        __syncthreads();
        for (int i = t; i < 512; i += 256) {
            int r = i >> 3, k4 = i & 7;
            float4 w4 = *(const float4*)(Wg + (size_t)(q0 + r) * TG2 + k0 + k4 * 4);
            Ws[k4 * 4 + 0][r] = w4.x; Ws[k4 * 4 + 1][r] = w4.y;
            Ws[k4 * 4 + 2][r] = w4.z; Ws[k4 * 4 + 3][r] = w4.w;
        }
        for (int i = t; i < 512; i += 256) {
            int kk = i >> 4, c4 = i & 15;
            *(float4*)&Vs[kk][c4 * 4] = *(const float4*)(Vg + (k0 + kk) * 64 + c4 * 4);
        }
        __syncthreads();
#pragma unroll 8
        for (int kk = 0; kk < 32; kk++) {
            float4 a4 = *(const float4*)&Ws[kk][ty * 4];
            float4 b4 = *(const float4*)&Vs[kk][tx * 4];
            float a[4] = {a4.x, a4.y, a4.z, a4.w};
            float bb[4] = {b4.x, b4.y, b4.z, b4.w};
#pragma unroll
            for (int i = 0; i < 4; i++)
#pragma unroll
                for (int j = 0; j < 4; j++) acc[i][j] += a[i] * bb[j];
        }
    }
#pragma unroll
    for (int i = 0; i < 4; i++)
        *(float4*)(g_hg + (size_t)(b * TG2 + q0 + ty * 4 + i) * 64 + tx * 4) =
            make_float4(acc[i][0], acc[i][1], acc[i][2], acc[i][3]);
}

// ---------------- K10: hp[s][q] = sum_k v[s][k]*wmT[k][q] ----------------
__global__ __launch_bounds__(224) void k_hp() {
    int b = blockIdx.y;
    int s0 = blockIdx.x * 64;
    __shared__ float As[28][64];
    __shared__ float Bs[28][196];
    const float* V   = g_v   + (size_t)b * NPB;
    const float* WMT = g_wmT + (size_t)b * P2 * P2;
    int t = threadIdx.x;
    int rg = t / 28, cg = t - (t / 28) * 28;
    float acc[8][7];
#pragma unroll
    for (int i = 0; i < 8; i++)
#pragma unroll
        for (int j = 0; j < 7; j++) acc[i][j] = 0.f;

    for (int k0 = 0; k0 < 196; k0 += 28) {
        __syncthreads();
        for (int i = t; i < 448; i += 224) {
            int r = i / 7, k4 = i - (i / 7) * 7;
            float4 vv = *(const float4*)(V + (size_t)(s0 + r) * 196 + k0 + k4 * 4);
            As[k4 * 4 + 0][r] = vv.x; As[k4 * 4 + 1][r] = vv.y;
            As[k4 * 4 + 2][r] = vv.z; As[k4 * 4 + 3][r] = vv.w;
        }
        for (int i = t; i < 1372; i += 224) {
            int kk = i / 49, c4 = i - (i / 49) * 49;
            *(float4*)&Bs[kk][c4 * 4] = *(const float4*)(WMT + (size_t)(k0 + kk) * 196 + c4 * 4);
        }
        __syncthreads();
#pragma unroll 4
        for (int kk = 0; kk < 28; kk++) {
            float4 a0 = *(const float4*)&As[kk][rg * 8];
            float4 a1 = *(const float4*)&As[kk][rg * 8 + 4];
            float a[8] = {a0.x, a0.y, a0.z, a0.w, a1.x, a1.y, a1.z, a1.w};
            float b7[7];
#pragma unroll
            for (int j = 0; j < 7; j++) b7[j] = Bs[kk][cg * 7 + j];
#pragma unroll
            for (int i = 0; i < 8; i++)
#pragma unroll
                for (int j = 0; j < 7; j++) acc[i][j] += a[i] * b7[j];
        }
    }
    float* O = g_hin + (size_t)b * NPB;
#pragma unroll
    for (int i = 0; i < 8; i++)
#pragma unroll
        for (int j = 0; j < 7; j++)
            O[(size_t)(s0 + rg * 8 + i) * 196 + cg * 7 + j] = acc[i][j];
}

// ---------------- K11: proj, 8x8 register blocking, fused blend + residual -----
__global__ __launch_bounds__(128) void k_proj(const float* __restrict__ x,
                                              const float* __restrict__ pw,
                                              float* __restrict__ out) {
    __shared__ float sH[64][128];
    __shared__ float sWt[64][64];
    int b = blockIdx.y;
    int pix0 = blockIdx.x * 128;
    int t = threadIdx.x;

    for (int i = t; i < 2048; i += 128) {
        int c = i >> 5, p4 = i & 31;
        int pgl = pix0 + p4 * 4;
        int h = pgl / WID, w = pgl - h * WID;
        int cell = (h >> 3) * 56 + (w >> 3);
        float4 hp = *(const float4*)(g_hin + (size_t)b * NPB + (size_t)c * HW + pgl);
        float hg = g_hg[(size_t)(b * TG2 + cell) * 64 + c] * 0.25f;
        float4 r = make_float4(0.75f * hp.x + hg, 0.75f * hp.y + hg,
                               0.75f * hp.z + hg, 0.75f * hp.w + hg);
        *(float4*)&sH[c][p4 * 4] = r;
    }
    for (int i = t; i < 1024; i += 128) {
        int o = i & 63, c4 = i >> 6;
        float4 w = *(const float4*)(pw + o * 64 + c4 * 4);
        sWt[c4 * 4 + 0][o] = w.x;
        sWt[c4 * 4 + 1][o] = w.y;
        sWt[c4 * 4 + 2][o] = w.z;
        sWt[c4 * 4 + 3][o] = w.w;
    }
    __syncthreads();

    int og = t >> 4, pg = t & 15;
    float acc[8][8];
#pragma unroll
    for (int i = 0; i < 8; i++)
#pragma unroll
        for (int j = 0; j < 8; j++) acc[i][j] = 0.f;

#pragma unroll 8
    for (int c = 0; c < 64; c++) {
        float4 x0 = *(const float4*)&sH[c][pg * 4];
        float4 x1 = *(const float4*)&sH[c][pg * 4 + 64];
        float4 w0 = *(const float4*)&sWt[c][og * 4];
        float4 w1 = *(const float4*)&sWt[c][og * 4 + 32];
        float a[8] = {w0.x, w0.y, w0.z, w0.w, w1.x, w1.y, w1.z, w1.w};
        float p[8] = {x0.x, x0.y, x0.z, x0.w, x1.x, x1.y, x1.z, x1.w};
#pragma unroll
        for (int i = 0; i < 8; i++)
#pragma unroll
            for (int j = 0; j < 8; j++) acc[i][j] += a[i] * p[j];
    }
#pragma unroll
    for (int i = 0; i < 8; i++) {
        int o = og * 4 + ((i < 4) ? i : 28 + i);
        size_t base = ((size_t)b * CC + o) * HW + pix0;
        float4 xr0 = *(const float4*)(x + base + pg * 4);
        float4 xr1 = *(const float4*)(x + base + 64 + pg * 4);
        *(float4*)(out + base + pg * 4) =
            make_float4(acc[i][0] + xr0.x, acc[i][1] + xr0.y, acc[i][2] + xr0.z, acc[i][3] + xr0.w);
        *(float4*)(out + base + 64 + pg * 4) =
            make_float4(acc[i][4] + xr1.x, acc[i][5] + xr1.y, acc[i][6] + xr1.z, acc[i][7] + xr1.w);
    }
}

extern "C" void kernel_launch(void* const* d_in, const int* in_sizes, int n_in,
                              void* d_out, int out_size) {
    const float* x   = (const float*)d_in[0];
    const float* gnw = (const float*)d_in[1];
    const float* gnb = (const float*)d_in[2];
    const float* qw  = (const float*)d_in[3];
    const float* qb  = (const float*)d_in[4];
    const float* kw  = (const float*)d_in[5];
    const float* kb  = (const float*)d_in[6];
    const float* vw  = (const float*)d_in[7];
    const float* vb  = (const float*)d_in[8];
    const float* pw  = (const float*)d_in[9];
    float* out = (float*)d_out;

    k_pool_stats<<<dim3(784, BATCH), 256>>>(x);
    k_stats2<<<BATCH, 256>>>();
    k_qkvg<<<dim3(TG2, BATCH), 64>>>(gnw, gnb, qw, qb, kw, kb, vw, vb);
    k_qkv<<<dim3(HW / 128, BATCH), 128>>>(x, gnw, gnb, qw, qb, kw, kb, vw, vb);
    k_wm<<<dim3(GRIDK, BATCH), 784>>>();
    k_softmax_wm<<<dim3(P2, BATCH), 256>>>();
    k_wg<<<dim3(TG2 / 64, TG2 / 64, BATCH), 256>>>();
    k_softmax_wg<<<dim3(TG2, BATCH), 256>>>();
    k_hg<<<dim3(TG2 / 64, BATCH), 256>>>();
    k_hp<<<dim3(SPB / 64, BATCH), 224>>>();
    k_proj<<<dim3(HW / 128, BATCH), 128>>>(x, pw, out);
}